// round 1
// baseline (speedup 1.0000x reference)
#include <cuda_runtime.h>
#include <cuda_bf16.h>
#include <math.h>

// ---------------------------------------------------------------------------
// WindowAttentionV2: B=2048 windows, N=64 tokens, C=256, H=8 heads, D=32
// Inputs (metadata order):
//  0 x            [2048,64,256] f32
//  1 mask         [256,64,64]   f32
//  2 qkv_w        [256,768]     f32
//  3 q_bias       [256]         f32
//  4 v_bias       [256]         f32
//  5 logit_scale  [8,1,1]       f32
//  6 coords_table [1,15,15,2]   f32
//  7 mlp1_w       [2,512]       f32
//  8 mlp1_b       [512]         f32
//  9 mlp2_w       [512,8]       f32
// 10 proj_w       [256,256]     f32
// 11 proj_b       [256]         f32
// 12 rel_pos_index[64,64]       i32
// out: [2048,64,256] f32
// ---------------------------------------------------------------------------

#define NWIN   2048
#define NTOK   64
#define CDIM   256
#define NHEAD  8
#define HDIM   32
#define TPB    384   // 12 warps

// Precomputed 16*sigmoid(cpb) bias: [H][64][64]
__device__ float g_rel_bias[NHEAD * NTOK * NTOK];

// ---------------------------------------------------------------------------
// Kernel 0: continuous position bias MLP (window-independent, tiny)
// ---------------------------------------------------------------------------
__global__ void cpb_kernel(const float* __restrict__ coords_table,
                           const float* __restrict__ mlp1_w,
                           const float* __restrict__ mlp1_b,
                           const float* __restrict__ mlp2_w,
                           const int*   __restrict__ rel_pos_index)
{
    __shared__ float bt[225 * 8];   // bias table [(2W-1)^2, H]
    int t = threadIdx.x;

    if (t < 225) {
        float c0 = coords_table[t * 2 + 0];
        float c1 = coords_table[t * 2 + 1];
        float acc[8];
#pragma unroll
        for (int hh = 0; hh < 8; hh++) acc[hh] = 0.f;
        for (int k = 0; k < 512; k++) {
            float hv = c0 * mlp1_w[k] + c1 * mlp1_w[512 + k] + mlp1_b[k];
            hv = fmaxf(hv, 0.f);
#pragma unroll
            for (int hh = 0; hh < 8; hh++) acc[hh] += hv * mlp2_w[k * 8 + hh];
        }
#pragma unroll
        for (int hh = 0; hh < 8; hh++) bt[t * 8 + hh] = acc[hh];
    }
    __syncthreads();

    // g_rel_bias[h][i][j] = 16 * sigmoid(bt[rpi[i*64+j]][h])
    for (int idx = t; idx < NHEAD * NTOK * NTOK; idx += blockDim.x) {
        int hh = idx >> 12;        // /4096
        int ij = idx & 4095;
        int p  = rel_pos_index[ij];
        float v = bt[p * 8 + hh];
        g_rel_bias[idx] = 16.f / (1.f + __expf(-v));
    }
}

// ---------------------------------------------------------------------------
// Kernel 1: fused per-window attention. One CTA per window, 384 threads.
// SMEM: XS[64][256], OUT[64][256], QS/KS/VS[64][33], ATT[64][65] = 169 KB
// ---------------------------------------------------------------------------
__global__ void __launch_bounds__(TPB, 1)
attn_kernel(const float* __restrict__ x,
            const float* __restrict__ mask,
            const float* __restrict__ qkv_w,
            const float* __restrict__ q_bias,
            const float* __restrict__ v_bias,
            const float* __restrict__ logit_scale,
            const float* __restrict__ proj_w,
            const float* __restrict__ proj_b,
            float*       __restrict__ out)
{
    extern __shared__ float sm[];
    float* XS  = sm;                    // [64][256]
    float* OUT = XS  + 64 * 256;        // [64][256]
    float* QS  = OUT + 64 * 256;        // [64][33]
    float* KS  = QS  + 64 * 33;
    float* VS  = KS  + 64 * 33;
    float* ATT = VS  + 64 * 33;         // [64][65]

    const int t    = threadIdx.x;
    const int lane = t & 31;
    const int w    = t >> 5;            // warp id 0..11
    const int bid  = blockIdx.x;
    const int win  = bid & 255;         // window index within image

    const float* xb = x    + (size_t)bid * (NTOK * CDIM);
    const float* mk = mask + (size_t)win * (NTOK * NTOK);

    // load x tile (coalesced float4)
    {
        const float4* src = (const float4*)xb;
        float4* dst = (float4*)XS;
        for (int i = t; i < NTOK * CDIM / 4; i += TPB) dst[i] = src[i];
    }
    __syncthreads();

    const int sec = w % 3;        // 0=q,1=k,2=v
    const int rg  = w / 3;        // row group 0..3
    const int n0  = rg * 16;

    for (int h = 0; h < NHEAD; h++) {
        // ---- Phase A: per-head qkv GEMM slice -----------------------------
        {
            const int gcol = sec * 256 + h * 32 + lane;
            const float* wp = qkv_w + gcol;
            float acc[16];
#pragma unroll
            for (int i = 0; i < 16; i++) acc[i] = 0.f;
            const float* xrow = XS + n0 * 256;
#pragma unroll 4
            for (int c = 0; c < 256; c++) {
                float wv = wp[(size_t)c * 768];
#pragma unroll
                for (int i = 0; i < 16; i++)
                    acc[i] += xrow[i * 256 + c] * wv;   // smem broadcast
            }
            float b = 0.f;
            if (sec == 0)      b = q_bias[h * 32 + lane];
            else if (sec == 2) b = v_bias[h * 32 + lane];
            float* dst = (sec == 0) ? QS : ((sec == 1) ? KS : VS);
#pragma unroll
            for (int i = 0; i < 16; i++)
                dst[(n0 + i) * 33 + lane] = acc[i] + b;
        }
        __syncthreads();

        // ---- Phase B: L2-normalize q (×scale) and k ------------------------
        {
            const float sc = __expf(fminf(logit_scale[h], 4.605170185988092f)); // log(100)
            if (t < 128) {
                int r = t & 63;
                float* P = (t < 64) ? QS : KS;
                float s = 0.f;
#pragma unroll
                for (int dd = 0; dd < 32; dd++) { float v = P[r * 33 + dd]; s += v * v; }
                float inv = 1.f / fmaxf(sqrtf(s), 1e-12f);
                if (t < 64) inv *= sc;
#pragma unroll
                for (int dd = 0; dd < 32; dd++) P[r * 33 + dd] *= inv;
            }
        }
        __syncthreads();

        // ---- Phase C: logits = qn·kn + rel_bias + mask ---------------------
        {
            const float* rb = g_rel_bias + h * 4096;
            for (int r = w; r < 64; r += 12) {
                float a0 = 0.f, a1 = 0.f;
#pragma unroll
                for (int dd = 0; dd < 32; dd++) {
                    float qv = QS[r * 33 + dd];
                    a0 += qv * KS[lane * 33 + dd];
                    a1 += qv * KS[(lane + 32) * 33 + dd];
                }
                int o = r * 64 + lane;
                a0 += rb[o]      + mk[o];
                a1 += rb[o + 32] + mk[o + 32];
                ATT[r * 65 + lane]      = a0;
                ATT[r * 65 + lane + 32] = a1;
            }
        }
        __syncthreads();

        // ---- Phase D: softmax per row --------------------------------------
        if (t < 64) {
            float m = -1e30f;
#pragma unroll 8
            for (int j = 0; j < 64; j++) m = fmaxf(m, ATT[t * 65 + j]);
            float s = 0.f;
#pragma unroll 8
            for (int j = 0; j < 64; j++) {
                float e = __expf(ATT[t * 65 + j] - m);
                ATT[t * 65 + j] = e;
                s += e;
            }
            float inv = 1.f / s;
#pragma unroll 8
            for (int j = 0; j < 64; j++) ATT[t * 65 + j] *= inv;
        }
        __syncthreads();

        // ---- Phase E: ctx = attn @ v ---------------------------------------
        for (int r = w; r < 64; r += 12) {
            float o = 0.f;
#pragma unroll
            for (int j = 0; j < 64; j++)
                o += ATT[r * 65 + j] * VS[j * 33 + lane];
            OUT[r * 256 + h * 32 + lane] = o;
        }
        __syncthreads();
    }

    // ---- Phase F: proj GEMM + bias -----------------------------------------
    float* dob = out + (size_t)bid * (NTOK * CDIM);
    for (int tt = w; tt < 16; tt += 12) {
        int r0 = tt * 4;
        float acc[4][8];
#pragma unroll
        for (int i = 0; i < 4; i++)
#pragma unroll
            for (int cb = 0; cb < 8; cb++) acc[i][cb] = 0.f;

#pragma unroll 2
        for (int c = 0; c < 256; c++) {
            float wv[8];
#pragma unroll
            for (int cb = 0; cb < 8; cb++)
                wv[cb] = proj_w[c * 256 + cb * 32 + lane];
#pragma unroll
            for (int i = 0; i < 4; i++) {
                float xv = OUT[(r0 + i) * 256 + c];   // smem broadcast
#pragma unroll
                for (int cb = 0; cb < 8; cb++) acc[i][cb] += xv * wv[cb];
            }
        }
#pragma unroll
        for (int i = 0; i < 4; i++)
#pragma unroll
            for (int cb = 0; cb < 8; cb++)
                dob[(r0 + i) * 256 + cb * 32 + lane] = acc[i][cb] + proj_b[cb * 32 + lane];
    }
}

// ---------------------------------------------------------------------------
extern "C" void kernel_launch(void* const* d_in, const int* in_sizes, int n_in,
                              void* d_out, int out_size)
{
    const float* x            = (const float*)d_in[0];
    const float* mask         = (const float*)d_in[1];
    const float* qkv_w        = (const float*)d_in[2];
    const float* q_bias       = (const float*)d_in[3];
    const float* v_bias       = (const float*)d_in[4];
    const float* logit_scale  = (const float*)d_in[5];
    const float* coords_table = (const float*)d_in[6];
    const float* mlp1_w       = (const float*)d_in[7];
    const float* mlp1_b       = (const float*)d_in[8];
    const float* mlp2_w       = (const float*)d_in[9];
    const float* proj_w       = (const float*)d_in[10];
    const float* proj_b       = (const float*)d_in[11];
    const int*   rel_pos_idx  = (const int*)d_in[12];
    float* out = (float*)d_out;

    const int smem_bytes = (64 * 256 * 2 + 64 * 33 * 3 + 64 * 65) * (int)sizeof(float);
    cudaFuncSetAttribute(attn_kernel, cudaFuncAttributeMaxDynamicSharedMemorySize, smem_bytes);

    cpb_kernel<<<1, 256>>>(coords_table, mlp1_w, mlp1_b, mlp2_w, rel_pos_idx);
    attn_kernel<<<NWIN, TPB, smem_bytes>>>(x, mask, qkv_w, q_bias, v_bias,
                                           logit_scale, proj_w, proj_b, out);
}

// round 2
// speedup vs baseline: 1.3193x; 1.3193x over previous
#include <cuda_runtime.h>
#include <cuda_bf16.h>
#include <math.h>

// ---------------------------------------------------------------------------
// WindowAttentionV2: B=2048 windows, N=64 tokens, C=256, H=8 heads, D=32
// Fully fused, fp32 with packed f32x2 FMA (FFMA2).
// ---------------------------------------------------------------------------

#define TPB 384   // 12 warps

__device__ float g_rel_bias[8 * 64 * 64];

__device__ __forceinline__ void ffma2(unsigned long long& d,
                                      unsigned long long a,
                                      unsigned long long b) {
    asm("fma.rn.f32x2 %0, %1, %2, %0;" : "+l"(d) : "l"(a), "l"(b));
}
__device__ __forceinline__ float hsum2(unsigned long long v) {
    union { unsigned long long u; float2 f; } c; c.u = v;
    return c.f.x + c.f.y;
}
__device__ __forceinline__ unsigned long long pack2(float lo, float hi) {
    union { unsigned long long u; float2 f; } c;
    c.f.x = lo; c.f.y = hi;
    return c.u;
}

// ---------------------------------------------------------------------------
// CPB MLP (window-independent): g_rel_bias[h][i][j] = 16*sigmoid(cpb)
// ---------------------------------------------------------------------------
__global__ void cpb_kernel(const float* __restrict__ coords_table,
                           const float* __restrict__ mlp1_w,
                           const float* __restrict__ mlp1_b,
                           const float* __restrict__ mlp2_w,
                           const int*   __restrict__ rel_pos_index)
{
    __shared__ float bt[225 * 8];
    int t = threadIdx.x;
    if (t < 225) {
        float c0 = coords_table[t * 2 + 0];
        float c1 = coords_table[t * 2 + 1];
        float acc[8];
#pragma unroll
        for (int hh = 0; hh < 8; hh++) acc[hh] = 0.f;
        for (int k = 0; k < 512; k++) {
            float hv = fmaxf(c0 * mlp1_w[k] + c1 * mlp1_w[512 + k] + mlp1_b[k], 0.f);
#pragma unroll
            for (int hh = 0; hh < 8; hh++) acc[hh] += hv * mlp2_w[k * 8 + hh];
        }
#pragma unroll
        for (int hh = 0; hh < 8; hh++) bt[t * 8 + hh] = acc[hh];
    }
    __syncthreads();
    for (int idx = t; idx < 8 * 64 * 64; idx += blockDim.x) {
        int hh = idx >> 12;
        int ij = idx & 4095;
        float v = bt[rel_pos_index[ij] * 8 + hh];
        g_rel_bias[idx] = 16.f / (1.f + __expf(-v));
    }
}

// ---------------------------------------------------------------------------
// Fused per-window attention. 1 CTA / window, 384 threads.
// SMEM floats: XS 16384 | OUT 16384 | QS 2304 | KS 2304 | VST 2176 | ATT 4096
//              | WS 12288 (as 6144 float2)  => 223744 bytes
// ---------------------------------------------------------------------------
__global__ void __launch_bounds__(TPB, 1)
attn_kernel(const float* __restrict__ x,
            const float* __restrict__ mask,
            const float* __restrict__ qkv_w,
            const float* __restrict__ q_bias,
            const float* __restrict__ v_bias,
            const float* __restrict__ logit_scale,
            const float* __restrict__ proj_w,
            const float* __restrict__ proj_b,
            float*       __restrict__ out)
{
    extern __shared__ float sm[];
    float* XS   = sm;                    // [64][256]
    float* OUTs = sm + 16384;            // [64][256]
    float* QS   = sm + 32768;            // [64][36]
    float* KS   = QS + 2304;             // [64][36]
    float* VST  = KS + 2304;             // [32][68] (v transposed)
    float* ATT  = VST + 2176;            // [64][64]
    unsigned long long* WS = (unsigned long long*)(ATT + 4096);  // 6144 float2

    const int t    = threadIdx.x;
    const int lane = t & 31;
    const int w    = t >> 5;
    const int bid  = blockIdx.x;
    const int win  = bid & 255;

    const float* xb = x    + (size_t)bid * 16384;
    const float* mk = mask + (size_t)win * 4096;

    // load x tile
    for (int i = t; i < 4096; i += TPB)
        ((float4*)XS)[i] = ((const float4*)xb)[i];
    // (first stage-sync below orders this)

    const int sec = w % 3;   // 0=q 1=k 2=v
    const int rg  = w / 3;
    const int n0  = rg * 16;

    for (int h = 0; h < 8; h++) {
        // ---- Phase A: qkv slice via packed FMA, weights staged in SMEM -----
        unsigned long long acc[16];
#pragma unroll
        for (int i = 0; i < 16; i++) acc[i] = 0ull;

        for (int kh = 0; kh < 2; kh++) {
            __syncthreads();   // prior WS/ATT consumers done
            // stage 128 input-channels x 96 qkv cols as float2 pairs
            for (int idx = t; idx < 6144; idx += TPB) {
                int cp  = idx / 96;            // channel pair 0..63
                int ci  = idx % 96;
                int s3  = ci >> 5;
                int gc  = s3 * 256 + h * 32 + (ci & 31);
                int c   = kh * 128 + cp * 2;
                WS[idx] = pack2(qkv_w[(size_t)c * 768 + gc],
                                qkv_w[(size_t)(c + 1) * 768 + gc]);
            }
            __syncthreads();

            const float* xbase = XS + n0 * 256 + kh * 128;
            const unsigned long long* wbase = WS + sec * 32 + lane;
#pragma unroll 4
            for (int cq = 0; cq < 32; cq++) {      // 4 channels per iter
                unsigned long long w0 = wbase[(2 * cq) * 96];
                unsigned long long w1 = wbase[(2 * cq + 1) * 96];
#pragma unroll
                for (int i = 0; i < 16; i++) {
                    ulonglong2 xv = *(const ulonglong2*)(xbase + i * 256 + cq * 4);
                    ffma2(acc[i], xv.x, w0);
                    ffma2(acc[i], xv.y, w1);
                }
            }
        }
        if (sec == 2) {
            float b = v_bias[h * 32 + lane];
#pragma unroll
            for (int i = 0; i < 16; i++)
                VST[lane * 68 + n0 + i] = hsum2(acc[i]) + b;
        } else {
            float b = (sec == 0) ? q_bias[h * 32 + lane] : 0.f;
            float* dst = (sec == 0) ? QS : KS;
#pragma unroll
            for (int i = 0; i < 16; i++)
                dst[(n0 + i) * 36 + lane] = hsum2(acc[i]) + b;
        }
        __syncthreads();

        // ---- Phase B: L2-normalize q (x scale) and k -----------------------
        if (t < 128) {
            int r = t & 63;
            float* P = (t < 64) ? QS : KS;
            float s = 0.f;
#pragma unroll
            for (int dd = 0; dd < 32; dd += 4) {
                float4 v = *(const float4*)&P[r * 36 + dd];
                s += v.x * v.x + v.y * v.y + v.z * v.z + v.w * v.w;
            }
            float inv = rsqrtf(fmaxf(s, 1e-24f));
            if (t < 64) inv *= __expf(fminf(logit_scale[h], 4.605170185988092f));
#pragma unroll
            for (int dd = 0; dd < 32; dd += 4) {
                float4 v = *(const float4*)&P[r * 36 + dd];
                v.x *= inv; v.y *= inv; v.z *= inv; v.w *= inv;
                *(float4*)&P[r * 36 + dd] = v;
            }
        }
        __syncthreads();

        // ---- Phase C+D: logits + bias + mask + in-warp softmax -------------
        const float* rb = g_rel_bias + h * 4096;
        for (int rp = w; rp < 32; rp += 12) {
            int r0 = rp * 2;
            unsigned long long a00 = 0, a01 = 0, a10 = 0, a11 = 0;
#pragma unroll
            for (int dd = 0; dd < 32; dd += 4) {
                ulonglong2 q0 = *(const ulonglong2*)&QS[r0 * 36 + dd];
                ulonglong2 q1 = *(const ulonglong2*)&QS[(r0 + 1) * 36 + dd];
                ulonglong2 k0 = *(const ulonglong2*)&KS[lane * 36 + dd];
                ulonglong2 k1 = *(const ulonglong2*)&KS[(lane + 32) * 36 + dd];
                ffma2(a00, q0.x, k0.x); ffma2(a00, q0.y, k0.y);
                ffma2(a01, q0.x, k1.x); ffma2(a01, q0.y, k1.y);
                ffma2(a10, q1.x, k0.x); ffma2(a10, q1.y, k0.y);
                ffma2(a11, q1.x, k1.x); ffma2(a11, q1.y, k1.y);
            }
#pragma unroll
            for (int rr = 0; rr < 2; rr++) {
                int r = r0 + rr;
                int o = r * 64 + lane;
                float v0 = hsum2(rr ? a10 : a00) + rb[o] + mk[o];
                float v1 = hsum2(rr ? a11 : a01) + rb[o + 32] + mk[o + 32];
                float m = fmaxf(v0, v1);
#pragma unroll
                for (int off = 16; off; off >>= 1)
                    m = fmaxf(m, __shfl_xor_sync(0xffffffffu, m, off));
                float e0 = __expf(v0 - m), e1 = __expf(v1 - m);
                float s = e0 + e1;
#pragma unroll
                for (int off = 16; off; off >>= 1)
                    s += __shfl_xor_sync(0xffffffffu, s, off);
                float inv = 1.f / s;
                ATT[o] = e0 * inv;
                ATT[o + 32] = e1 * inv;
            }
        }
        __syncthreads();

        // ---- Phase E: ctx = P @ V ------------------------------------------
        for (int g = w; g < 16; g += 12) {
            int r0 = g * 4;
            unsigned long long o0 = 0, o1 = 0, o2 = 0, o3 = 0;
#pragma unroll
            for (int j = 0; j < 64; j += 4) {
                ulonglong2 vv = *(const ulonglong2*)&VST[lane * 68 + j];
                ulonglong2 p0 = *(const ulonglong2*)&ATT[(r0 + 0) * 64 + j];
                ulonglong2 p1 = *(const ulonglong2*)&ATT[(r0 + 1) * 64 + j];
                ulonglong2 p2 = *(const ulonglong2*)&ATT[(r0 + 2) * 64 + j];
                ulonglong2 p3 = *(const ulonglong2*)&ATT[(r0 + 3) * 64 + j];
                ffma2(o0, p0.x, vv.x); ffma2(o0, p0.y, vv.y);
                ffma2(o1, p1.x, vv.x); ffma2(o1, p1.y, vv.y);
                ffma2(o2, p2.x, vv.x); ffma2(o2, p2.y, vv.y);
                ffma2(o3, p3.x, vv.x); ffma2(o3, p3.y, vv.y);
            }
            OUTs[(r0 + 0) * 256 + h * 32 + lane] = hsum2(o0);
            OUTs[(r0 + 1) * 256 + h * 32 + lane] = hsum2(o1);
            OUTs[(r0 + 2) * 256 + h * 32 + lane] = hsum2(o2);
            OUTs[(r0 + 3) * 256 + h * 32 + lane] = hsum2(o3);
        }
        __syncthreads();
    }

    // ---- Phase F: proj GEMM, 2 col-passes x 4 K-chunks staged in XS --------
    unsigned long long* WP = (unsigned long long*)XS;   // 8192 float2 = 64KB
    int nr, rbase;
    if (w < 4) { nr = 6; rbase = w * 6; }
    else       { nr = 5; rbase = 24 + (w - 4) * 5; }
    float* dob = out + (size_t)bid * 16384;

    for (int pass = 0; pass < 2; pass++) {
        const int c0col = pass * 128;
        unsigned long long acc[6][4];
#pragma unroll
        for (int i = 0; i < 6; i++)
#pragma unroll
            for (int cb = 0; cb < 4; cb++) acc[i][cb] = 0ull;

        for (int ch = 0; ch < 4; ch++) {
            __syncthreads();
            for (int idx = t; idx < 8192; idx += TPB) {
                int cp  = idx >> 8;
                int col = idx & 255;
                int c   = ch * 64 + cp * 2;
                WP[idx] = pack2(proj_w[(size_t)c * 256 + col],
                                proj_w[(size_t)(c + 1) * 256 + col]);
            }
            __syncthreads();
#pragma unroll 2
            for (int cp = 0; cp < 32; cp++) {
                unsigned long long wv[4];
#pragma unroll
                for (int cb = 0; cb < 4; cb++)
                    wv[cb] = WP[cp * 256 + c0col + cb * 32 + lane];
#pragma unroll
                for (int i = 0; i < 6; i++) {
                    if (i < nr) {
                        unsigned long long xp =
                            *(const unsigned long long*)&OUTs[(rbase + i) * 256 + ch * 64 + 2 * cp];
#pragma unroll
                        for (int cb = 0; cb < 4; cb++) ffma2(acc[i][cb], xp, wv[cb]);
                    }
                }
            }
        }
#pragma unroll
        for (int i = 0; i < 6; i++) {
            if (i < nr) {
#pragma unroll
                for (int cb = 0; cb < 4; cb++) {
                    int col = c0col + cb * 32 + lane;
                    dob[(rbase + i) * 256 + col] = hsum2(acc[i][cb]) + proj_b[col];
                }
            }
        }
    }
}

// ---------------------------------------------------------------------------
extern "C" void kernel_launch(void* const* d_in, const int* in_sizes, int n_in,
                              void* d_out, int out_size)
{
    const float* x            = (const float*)d_in[0];
    const float* mask         = (const float*)d_in[1];
    const float* qkv_w        = (const float*)d_in[2];
    const float* q_bias       = (const float*)d_in[3];
    const float* v_bias       = (const float*)d_in[4];
    const float* logit_scale  = (const float*)d_in[5];
    const float* coords_table = (const float*)d_in[6];
    const float* mlp1_w       = (const float*)d_in[7];
    const float* mlp1_b       = (const float*)d_in[8];
    const float* mlp2_w       = (const float*)d_in[9];
    const float* proj_w       = (const float*)d_in[10];
    const float* proj_b       = (const float*)d_in[11];
    const int*   rel_pos_idx  = (const int*)d_in[12];
    float* out = (float*)d_out;

    const int smem_bytes = 223744;
    cudaFuncSetAttribute(attn_kernel, cudaFuncAttributeMaxDynamicSharedMemorySize, smem_bytes);

    cpb_kernel<<<1, 256>>>(coords_table, mlp1_w, mlp1_b, mlp2_w, rel_pos_idx);
    attn_kernel<<<2048, TPB, smem_bytes>>>(x, mask, qkv_w, q_bias, v_bias,
                                           logit_scale, proj_w, proj_b, out);
}

// round 4
// speedup vs baseline: 3.5899x; 2.7211x over previous
#include <cuda_runtime.h>
#include <cuda_bf16.h>
#include <cstdint>
#include <math.h>

// ===========================================================================
// WindowAttentionV2 via mma.sync bf16 split (hi/lo) GEMMs + fp32 attention.
// B=2048 win, N=64 tok, C=256, H=8, D=32.
// ===========================================================================

// ---- device scratch --------------------------------------------------------
__device__ float g_qkv[3u * 2048 * 8 * 2048];          // [(sec*2048+win)*8+h][tok*32+d]
__device__ __nv_bfloat16 g_xhi[131072u * 256];
__device__ __nv_bfloat16 g_xlo[131072u * 256];
__device__ __nv_bfloat16 g_chi[131072u * 256];
__device__ __nv_bfloat16 g_clo[131072u * 256];
__device__ __nv_bfloat16 g_wqkv_hi[768 * 256];         // [n][k]
__device__ __nv_bfloat16 g_wqkv_lo[768 * 256];
__device__ __nv_bfloat16 g_wproj_hi[256 * 256];
__device__ __nv_bfloat16 g_wproj_lo[256 * 256];
__device__ float g_rel_bias[8 * 64 * 64];
__device__ float g_bias_qkv[768];

// ---- helpers ----------------------------------------------------------------
__device__ __forceinline__ void ffma2(unsigned long long& d,
                                      unsigned long long a,
                                      unsigned long long b) {
    asm("fma.rn.f32x2 %0, %1, %2, %0;" : "+l"(d) : "l"(a), "l"(b));
}
__device__ __forceinline__ float hsum2(unsigned long long v) {
    union { unsigned long long u; float2 f; } c; c.u = v;
    return c.f.x + c.f.y;
}
__device__ __forceinline__ uint32_t smem_u32(const void* p) {
    uint32_t a;
    asm("{ .reg .u64 t; cvta.to.shared.u64 t, %1; cvt.u32.u64 %0, t; }"
        : "=r"(a) : "l"(p));
    return a;
}
__device__ __forceinline__ void mma_bf16(float* c, const uint32_t* a, const uint32_t* b) {
    asm volatile(
        "mma.sync.aligned.m16n8k16.row.col.f32.bf16.bf16.f32 "
        "{%0,%1,%2,%3}, {%4,%5,%6,%7}, {%8,%9}, {%0,%1,%2,%3};"
        : "+f"(c[0]), "+f"(c[1]), "+f"(c[2]), "+f"(c[3])
        : "r"(a[0]), "r"(a[1]), "r"(a[2]), "r"(a[3]), "r"(b[0]), "r"(b[1]));
}
__device__ __forceinline__ void ldm4(uint32_t* r, uint32_t addr) {
    asm volatile("ldmatrix.sync.aligned.m8n8.x4.shared.b16 {%0,%1,%2,%3}, [%4];"
                 : "=r"(r[0]), "=r"(r[1]), "=r"(r[2]), "=r"(r[3]) : "r"(addr));
}
__device__ __forceinline__ void cpasync16(uint32_t dst, const void* src) {
    asm volatile("cp.async.cg.shared.global [%0], [%1], 16;" :: "r"(dst), "l"(src));
}
__device__ __forceinline__ void bf_split(float v, __nv_bfloat16& hi, __nv_bfloat16& lo) {
    hi = __float2bfloat16(v);
    lo = __float2bfloat16(v - __bfloat162float(hi));
}

// ===========================================================================
// prep_x: x fp32 -> bf16 hi/lo
// ===========================================================================
__global__ void prep_x_kernel(const float* __restrict__ x)
{
    int gid = blockIdx.x * blockDim.x + threadIdx.x;
    int gsz = gridDim.x * blockDim.x;
    for (int i = gid; i < 131072 * 64; i += gsz) {     // 8.39M float4
        float4 f = ((const float4*)x)[i];
        __nv_bfloat16 h0, h1, h2, h3, l0, l1, l2, l3;
        bf_split(f.x, h0, l0); bf_split(f.y, h1, l1);
        bf_split(f.z, h2, l2); bf_split(f.w, h3, l3);
        ((__nv_bfloat162*)g_xhi)[2 * i]     = __nv_bfloat162(h0, h1);
        ((__nv_bfloat162*)g_xhi)[2 * i + 1] = __nv_bfloat162(h2, h3);
        ((__nv_bfloat162*)g_xlo)[2 * i]     = __nv_bfloat162(l0, l1);
        ((__nv_bfloat162*)g_xlo)[2 * i + 1] = __nv_bfloat162(l2, l3);
    }
}

// ===========================================================================
// prep_w: weights -> [n][k] bf16 hi/lo, qkv bias pack
// ===========================================================================
__global__ void prep_w_kernel(const float* __restrict__ qkv_w,
                              const float* __restrict__ proj_w,
                              const float* __restrict__ q_bias,
                              const float* __restrict__ v_bias)
{
    int gid = blockIdx.x * blockDim.x + threadIdx.x;
    int gsz = gridDim.x * blockDim.x;
    for (int i = gid; i < 768 * 256; i += gsz) {
        int n = i >> 8, k = i & 255;
        __nv_bfloat16 hi, lo;
        bf_split(qkv_w[(size_t)k * 768 + n], hi, lo);
        g_wqkv_hi[i] = hi; g_wqkv_lo[i] = lo;
    }
    for (int i = gid; i < 256 * 256; i += gsz) {
        int n = i >> 8, k = i & 255;
        __nv_bfloat16 hi, lo;
        bf_split(proj_w[(size_t)k * 256 + n], hi, lo);
        g_wproj_hi[i] = hi; g_wproj_lo[i] = lo;
    }
    for (int i = gid; i < 768; i += gsz)
        g_bias_qkv[i] = (i < 256) ? q_bias[i] : ((i < 512) ? 0.f : v_bias[i - 512]);
}

// ===========================================================================
// cpb: continuous position bias (window-independent)
// ===========================================================================
__global__ void cpb_kernel(const float* __restrict__ coords_table,
                           const float* __restrict__ mlp1_w,
                           const float* __restrict__ mlp1_b,
                           const float* __restrict__ mlp2_w,
                           const int*   __restrict__ rel_pos_index)
{
    __shared__ float bt[225 * 8];
    int t = threadIdx.x;
    if (t < 225) {
        float c0 = coords_table[t * 2 + 0];
        float c1 = coords_table[t * 2 + 1];
        float acc[8];
#pragma unroll
        for (int hh = 0; hh < 8; hh++) acc[hh] = 0.f;
        for (int k = 0; k < 512; k++) {
            float hv = fmaxf(c0 * mlp1_w[k] + c1 * mlp1_w[512 + k] + mlp1_b[k], 0.f);
#pragma unroll
            for (int hh = 0; hh < 8; hh++) acc[hh] += hv * mlp2_w[k * 8 + hh];
        }
#pragma unroll
        for (int hh = 0; hh < 8; hh++) bt[t * 8 + hh] = acc[hh];
    }
    __syncthreads();
    for (int idx = t; idx < 8 * 64 * 64; idx += blockDim.x) {
        int hh = idx >> 12;
        int ij = idx & 4095;
        float v = bt[rel_pos_index[ij] * 8 + hh];
        g_rel_bias[idx] = 16.f / (1.f + __expf(-v));
    }
}

// ===========================================================================
// gemm_mma: C[128, 128] tile of A[131072,256] @ B^T[256, N], split bf16.
// MODE 0: A = x hi/lo, B = qkv weights, epilogue scatter -> g_qkv (+qkv bias)
// MODE 1: A = ctx hi/lo, B = proj weights, epilogue -> out (+proj bias)
// Block: 256 thr = 8 warps (4m x 2n), warp tile 32x64.
// ===========================================================================
#define LDS 72

template<int MODE>
__global__ void __launch_bounds__(256, 2)
gemm_mma_kernel(const float* __restrict__ bias_ext, float* __restrict__ Cout)
{
    extern __shared__ __nv_bfloat16 smb[];
    const uint32_t sb = smem_u32(smb);
    const uint32_t AH = sb;
    const uint32_t AL = AH + 128 * LDS * 2;
    const uint32_t BH = AL + 128 * LDS * 2;
    const uint32_t BL = BH + 128 * LDS * 2;

    const int t = threadIdx.x, lane = t & 31, w = t >> 5;
    const int wm = w & 3, wn = w >> 2;
    const int mtile = blockIdx.x, ntile = blockIdx.y;

    const __nv_bfloat16 *gAh, *gAl, *gBh, *gBl;
    if (MODE == 0) { gAh = g_xhi; gAl = g_xlo; gBh = g_wqkv_hi; gBl = g_wqkv_lo; }
    else           { gAh = g_chi; gAl = g_clo; gBh = g_wproj_hi; gBl = g_wproj_lo; }

    const size_t aoff = (size_t)mtile * 128 * 256;
    const size_t boff = (size_t)ntile * 128 * 256;

    float acc[2][8][4];
#pragma unroll
    for (int mi = 0; mi < 2; mi++)
#pragma unroll
        for (int n8 = 0; n8 < 8; n8++)
#pragma unroll
            for (int r = 0; r < 4; r++) acc[mi][n8][r] = 0.f;

    // staging decomposition: idx -> (row, colgroup)
    const int r0 = t >> 3, cg = t & 7;   // rep stride adds 32 rows

    for (int kc = 0; kc < 4; kc++) {
        const int k0 = kc * 64;
#pragma unroll
        for (int rep = 0; rep < 4; rep++) {
            int r = r0 + rep * 32;
            uint32_t so = (uint32_t)(r * LDS + cg * 8) * 2;
            size_t go = (size_t)r * 256 + k0 + cg * 8;
            cpasync16(AH + so, gAh + aoff + go);
            cpasync16(AL + so, gAl + aoff + go);
            cpasync16(BH + so, gBh + boff + go);
            cpasync16(BL + so, gBl + boff + go);
        }
        asm volatile("cp.async.commit_group;" ::: "memory");
        asm volatile("cp.async.wait_group 0;" ::: "memory");
        __syncthreads();

#pragma unroll
        for (int ks = 0; ks < 4; ks++) {
            uint32_t ah[2][4], al[2][4];
            {
                int arow = wm * 32 + (lane & 15);
                int acol = ks * 16 + ((lane >> 4) << 3);
                uint32_t ao = (uint32_t)(arow * LDS + acol) * 2;
                ldm4(ah[0], AH + ao);
                ldm4(ah[1], AH + ao + 16 * LDS * 2);
                ldm4(al[0], AL + ao);
                ldm4(al[1], AL + ao + 16 * LDS * 2);
            }
            const int quad = lane >> 3, l8 = lane & 7;
            const int bcol = ks * 16 + ((quad & 1) << 3);
#pragma unroll
            for (int np = 0; np < 4; np++) {
                int brow = wn * 64 + np * 16 + ((quad >> 1) << 3) + l8;
                uint32_t bo = (uint32_t)(brow * LDS + bcol) * 2;
                uint32_t bq[4];
                ldm4(bq, BH + bo);                       // 2 n8-tiles of B-hi
#pragma unroll
                for (int mi = 0; mi < 2; mi++) {
                    mma_bf16(acc[mi][2 * np + 0], ah[mi], bq + 0);  // hi*whi
                    mma_bf16(acc[mi][2 * np + 1], ah[mi], bq + 2);
                    mma_bf16(acc[mi][2 * np + 0], al[mi], bq + 0);  // lo*whi
                    mma_bf16(acc[mi][2 * np + 1], al[mi], bq + 2);
                }
                ldm4(bq, BL + bo);                       // B-lo
#pragma unroll
                for (int mi = 0; mi < 2; mi++) {
                    mma_bf16(acc[mi][2 * np + 0], ah[mi], bq + 0);  // hi*wlo
                    mma_bf16(acc[mi][2 * np + 1], ah[mi], bq + 2);
                }
            }
        }
        __syncthreads();
    }

    // ---- epilogue -----------------------------------------------------------
    const int row_l = wm * 32 + (lane >> 2);
    const int col_l = wn * 64 + (lane & 3) * 2;
#pragma unroll
    for (int mi = 0; mi < 2; mi++) {
#pragma unroll
        for (int n8 = 0; n8 < 8; n8++) {
            int gc = ntile * 128 + col_l + n8 * 8;
            if (MODE == 0) {
                int sec = gc >> 8, hh = (gc >> 5) & 7, d = gc & 31;
                float b0 = g_bias_qkv[gc], b1 = g_bias_qkv[gc + 1];
#pragma unroll
                for (int half = 0; half < 2; half++) {
                    int row = mtile * 128 + row_l + mi * 16 + half * 8;
                    int win = row >> 6, tok = row & 63;
                    size_t addr = (((size_t)sec * 2048 + win) * 8 + hh) * 2048
                                  + (size_t)tok * 32 + d;
                    float2 v;
                    v.x = acc[mi][n8][2 * half + 0] + b0;
                    v.y = acc[mi][n8][2 * half + 1] + b1;
                    *(float2*)&g_qkv[addr] = v;
                }
            } else {
                float b0 = bias_ext[gc], b1 = bias_ext[gc + 1];
#pragma unroll
                for (int half = 0; half < 2; half++) {
                    int row = mtile * 128 + row_l + mi * 16 + half * 8;
                    float2 v;
                    v.x = acc[mi][n8][2 * half + 0] + b0;
                    v.y = acc[mi][n8][2 * half + 1] + b1;
                    *(float2*)&Cout[(size_t)row * 256 + gc] = v;
                }
            }
        }
    }
}

// ===========================================================================
// attention middle (normalize, QK^T, softmax, PV). CTA = (win, head).
// Writes ctx as bf16 hi/lo for the proj GEMM.
// ===========================================================================
__global__ void __launch_bounds__(128)
attn2_kernel(const float* __restrict__ mask,
             const float* __restrict__ logit_scale)
{
    __shared__ float Q[64 * 36];
    __shared__ float K[64 * 36];
    __shared__ float VT[32 * 68];
    __shared__ float P[64 * 64];

    const int t = threadIdx.x, lane = t & 31, w = t >> 5;
    const int bid = blockIdx.x;
    const int win = bid >> 3, h = bid & 7;

    const size_t qb = (((size_t)0 * 2048 + win) * 8 + h) * 2048;
    const size_t kb = (((size_t)1 * 2048 + win) * 8 + h) * 2048;
    const size_t vb = (((size_t)2 * 2048 + win) * 8 + h) * 2048;

    for (int i = t; i < 512; i += 128) {
        float4 fq = *(const float4*)&g_qkv[qb + (size_t)i * 4];
        float4 fk = *(const float4*)&g_qkv[kb + (size_t)i * 4];
        float4 fv = *(const float4*)&g_qkv[vb + (size_t)i * 4];
        int tok = i >> 3, dg = (i & 7) * 4;
        *(float4*)&Q[tok * 36 + dg] = fq;
        *(float4*)&K[tok * 36 + dg] = fk;
        VT[(dg + 0) * 68 + tok] = fv.x;
        VT[(dg + 1) * 68 + tok] = fv.y;
        VT[(dg + 2) * 68 + tok] = fv.z;
        VT[(dg + 3) * 68 + tok] = fv.w;
    }
    __syncthreads();

    {
        int r = t & 63;
        float* Pm = (t < 64) ? Q : K;
        float s = 0.f;
#pragma unroll
        for (int dd = 0; dd < 32; dd += 4) {
            float4 v = *(const float4*)&Pm[r * 36 + dd];
            s += v.x * v.x + v.y * v.y + v.z * v.z + v.w * v.w;
        }
        float inv = rsqrtf(fmaxf(s, 1e-24f));
        if (t < 64) inv *= __expf(fminf(logit_scale[h], 4.605170185988092f));
#pragma unroll
        for (int dd = 0; dd < 32; dd += 4) {
            float4 v = *(const float4*)&Pm[r * 36 + dd];
            v.x *= inv; v.y *= inv; v.z *= inv; v.w *= inv;
            *(float4*)&Pm[r * 36 + dd] = v;
        }
    }
    __syncthreads();

    const float* rb = g_rel_bias + h * 4096;
    const float* mk = mask + (size_t)(win & 255) * 4096;
    for (int p4 = 0; p4 < 4; p4++) {
        int r0 = w * 16 + p4 * 4;
        unsigned long long a[4][2];
#pragma unroll
        for (int rr = 0; rr < 4; rr++) { a[rr][0] = 0ull; a[rr][1] = 0ull; }
#pragma unroll
        for (int dd = 0; dd < 32; dd += 4) {
            ulonglong2 k0 = *(const ulonglong2*)&K[lane * 36 + dd];
            ulonglong2 k1 = *(const ulonglong2*)&K[(lane + 32) * 36 + dd];
#pragma unroll
            for (int rr = 0; rr < 4; rr++) {
                ulonglong2 qv = *(const ulonglong2*)&Q[(r0 + rr) * 36 + dd];
                ffma2(a[rr][0], qv.x, k0.x); ffma2(a[rr][0], qv.y, k0.y);
                ffma2(a[rr][1], qv.x, k1.x); ffma2(a[rr][1], qv.y, k1.y);
            }
        }
#pragma unroll
        for (int rr = 0; rr < 4; rr++) {
            int r = r0 + rr, o = r * 64 + lane;
            float v0 = hsum2(a[rr][0]) + rb[o] + mk[o];
            float v1 = hsum2(a[rr][1]) + rb[o + 32] + mk[o + 32];
            float m = fmaxf(v0, v1);
#pragma unroll
            for (int off = 16; off; off >>= 1)
                m = fmaxf(m, __shfl_xor_sync(0xffffffffu, m, off));
            float e0 = __expf(v0 - m), e1 = __expf(v1 - m);
            float s = e0 + e1;
#pragma unroll
            for (int off = 16; off; off >>= 1)
                s += __shfl_xor_sync(0xffffffffu, s, off);
            float inv = 1.f / s;
            P[o] = e0 * inv;
            P[o + 32] = e1 * inv;
        }
    }
    __syncthreads();

    size_t cbase = ((size_t)win * 64) * 256 + h * 32 + lane;
    for (int p8 = 0; p8 < 2; p8++) {
        int r0 = w * 16 + p8 * 8;
        unsigned long long acc[8];
#pragma unroll
        for (int rr = 0; rr < 8; rr++) acc[rr] = 0ull;
#pragma unroll
        for (int j = 0; j < 64; j += 4) {
            ulonglong2 vv = *(const ulonglong2*)&VT[lane * 68 + j];
#pragma unroll
            for (int rr = 0; rr < 8; rr++) {
                ulonglong2 pp = *(const ulonglong2*)&P[(r0 + rr) * 64 + j];
                ffma2(acc[rr], pp.x, vv.x);
                ffma2(acc[rr], pp.y, vv.y);
            }
        }
#pragma unroll
        for (int rr = 0; rr < 8; rr++) {
            float o = hsum2(acc[rr]);
            __nv_bfloat16 hi, lo;
            bf_split(o, hi, lo);
            size_t idx = cbase + (size_t)(r0 + rr) * 256;
            g_chi[idx] = hi;
            g_clo[idx] = lo;
        }
    }
}

// ===========================================================================
extern "C" void kernel_launch(void* const* d_in, const int* in_sizes, int n_in,
                              void* d_out, int out_size)
{
    const float* x            = (const float*)d_in[0];
    const float* mask         = (const float*)d_in[1];
    const float* qkv_w        = (const float*)d_in[2];
    const float* q_bias       = (const float*)d_in[3];
    const float* v_bias       = (const float*)d_in[4];
    const float* logit_scale  = (const float*)d_in[5];
    const float* coords_table = (const float*)d_in[6];
    const float* mlp1_w       = (const float*)d_in[7];
    const float* mlp1_b       = (const float*)d_in[8];
    const float* mlp2_w       = (const float*)d_in[9];
    const float* proj_w       = (const float*)d_in[10];
    const float* proj_b       = (const float*)d_in[11];
    const int*   rel_pos_idx  = (const int*)d_in[12];
    float* out = (float*)d_out;

    const int smem_g = 4 * 128 * LDS * 2;   // 73728
    cudaFuncSetAttribute(gemm_mma_kernel<0>,
                         cudaFuncAttributeMaxDynamicSharedMemorySize, smem_g);
    cudaFuncSetAttribute(gemm_mma_kernel<1>,
                         cudaFuncAttributeMaxDynamicSharedMemorySize, smem_g);

    prep_x_kernel<<<4096, 256>>>(x);
    prep_w_kernel<<<256, 256>>>(qkv_w, proj_w, q_bias, v_bias);
    cpb_kernel<<<1, 256>>>(coords_table, mlp1_w, mlp1_b, mlp2_w, rel_pos_idx);
    gemm_mma_kernel<0><<<dim3(1024, 6), 256, smem_g>>>(nullptr, nullptr);
    attn2_kernel<<<2048 * 8, 128>>>(mask, logit_scale);
    gemm_mma_kernel<1><<<dim3(1024, 2), 256, smem_g>>>(proj_b, out);
}